// round 7
// baseline (speedup 1.0000x reference)
#include <cuda_runtime.h>
#include <cstddef>

// JPEG 8x8 blockify + orthonormal 2D DCT-II + QF quantization.
// image: [16,1,1024,1024] f32, qf: [16] f32 -> out [16,64,128,128] f32.
//
// R7: R5 thread-split (2 threads per 8x8 block, shuffle-pair row DCT) +
// cp.async double-buffered chunk pipeline. A chunk = one block-row
// (128 blocks, 32KB contiguous input). Each CTA grid-strides over chunks,
// prefetching chunk i+1 via cp.async while computing chunk i from smem.
// Staged data is thread-private (144B stride -> conflict-free LDS.128),
// so there are NO barriers: warps drift, smoothing DRAM read duty cycle.

#define A0 0.35355339059327373f  // 1/sqrt(8)
#define H1 0.49039264020161522f  // cos(1*pi/16)/2
#define H2 0.46193976625564337f  // cos(2*pi/16)/2
#define H3 0.41573480615127262f  // cos(3*pi/16)/2
#define H4 0.35355339059327376f  // cos(4*pi/16)/2
#define H5 0.27778511650980111f  // cos(5*pi/16)/2
#define H6 0.19134171618254489f  // cos(6*pi/16)/2
#define H7 0.09754516100806413f  // cos(7*pi/16)/2

// 100 / qtab  (scale numerator; divided by per-image "factor" at runtime)
__constant__ float c_qinv[64] = {
    100.f/16.f, 100.f/11.f, 100.f/10.f, 100.f/16.f, 100.f/24.f, 100.f/40.f, 100.f/51.f, 100.f/61.f,
    100.f/12.f, 100.f/12.f, 100.f/14.f, 100.f/19.f, 100.f/26.f, 100.f/58.f, 100.f/60.f, 100.f/55.f,
    100.f/14.f, 100.f/13.f, 100.f/16.f, 100.f/24.f, 100.f/40.f, 100.f/57.f, 100.f/69.f, 100.f/56.f,
    100.f/14.f, 100.f/17.f, 100.f/22.f, 100.f/29.f, 100.f/51.f, 100.f/87.f, 100.f/80.f, 100.f/62.f,
    100.f/18.f, 100.f/22.f, 100.f/37.f, 100.f/56.f, 100.f/68.f, 100.f/109.f, 100.f/103.f, 100.f/77.f,
    100.f/24.f, 100.f/36.f, 100.f/55.f, 100.f/64.f, 100.f/81.f, 100.f/104.f, 100.f/113.f, 100.f/92.f,
    100.f/49.f, 100.f/64.f, 100.f/78.f, 100.f/87.f, 100.f/103.f, 100.f/121.f, 100.f/120.f, 100.f/101.f,
    100.f/72.f, 100.f/92.f, 100.f/95.f, 100.f/98.f, 100.f/112.f, 100.f/100.f, 100.f/103.f, 100.f/99.f};

__device__ __forceinline__ void dct8(float& x0, float& x1, float& x2, float& x3,
                                     float& x4, float& x5, float& x6, float& x7) {
    float e0 = x0 + x7, e1 = x1 + x6, e2 = x2 + x5, e3 = x3 + x4;
    float o0 = x0 - x7, o1 = x1 - x6, o2 = x2 - x5, o3 = x3 - x4;
    float ee0 = e0 + e3, ee1 = e1 + e2;
    float eo0 = e0 - e3, eo1 = e1 - e2;
    x0 = A0 * (ee0 + ee1);
    x4 = H4 * (ee0 - ee1);
    x2 = H2 * eo0 + H6 * eo1;
    x6 = H6 * eo0 - H2 * eo1;
    x1 = H1 * o0 + H3 * o1 + H5 * o2 + H7 * o3;
    x3 = H3 * o0 - H7 * o1 - H1 * o2 - H5 * o3;
    x5 = H5 * o0 - H1 * o1 + H7 * o2 + H3 * o3;
    x7 = H7 * o0 - H5 * o1 + H3 * o2 - H1 * o3;
}

#define NCHUNK 2048            // 16 images * 128 block-rows
#define TSTRIDE_B 144          // bytes per thread in a stage (8*16B + 16B pad)
#define STAGE_B (256 * TSTRIDE_B)  // 36864 B per stage

__device__ __forceinline__ void prefetch_chunk(const float* __restrict__ img,
                                               int s, unsigned sm_base, int tid) {
    // chunk s: image b = s>>7, block-row hb = s&127.
    int b = s >> 7;
    int hb = s & 127;
    int wb = tid >> 1;
    int h = tid & 1;
    const float* g = img + ((size_t)b << 20) + (size_t)hb * 8192 + wb * 8 + h * 4;
    unsigned dst = sm_base + tid * TSTRIDE_B;
#pragma unroll
    for (int r = 0; r < 8; r++) {
        asm volatile("cp.async.ca.shared.global [%0], [%1], 16;\n"
                     :: "r"(dst + r * 16), "l"(g + (size_t)r * 1024) : "memory");
    }
}

extern __shared__ float smem_dyn[];

__global__ __launch_bounds__(256) void jpeg_dct_kernel(
    const float* __restrict__ img,
    const float* __restrict__ qf,
    float* __restrict__ out) {
    int tid = threadIdx.x;
    unsigned sm_base;
    asm("{ .reg .u64 t; cvta.to.shared.u64 t, %1; cvt.u32.u64 %0, t; }"
        : "=r"(sm_base) : "l"(smem_dyn));

    int q = tid & 1;         // half: columns 4q..4q+3
    int wb = tid >> 1;       // block column within the chunk's row

    // Per-half row-transform coefficients (selected once).
    bool hi = (q != 0);
    float cA0 = hi ?  H4 :  A0, cA1 = hi ? -H4 :  A0;   // l = 4q+0
    float cB0 = hi ? -H6 :  H2, cB1 = hi ?  H2 :  H6;   // l = 4q+2
    float cC0 = hi ? -H3 :  H1, cC1 = hi ? -H7 :  H3,   // l = 4q+1
          cC2 = hi ?  H1 :  H5, cC3 = hi ? -H5 :  H7;
    float cD0 = hi ?  H1 :  H3, cD1 = hi ? -H3 : -H7,   // l = 4q+3
          cD2 = hi ?  H5 : -H1, cD3 = hi ? -H7 : -H5;

    int s = blockIdx.x;
    prefetch_chunk(img, s, sm_base, tid);
    asm volatile("cp.async.commit_group;\n" ::: "memory");

    int cur = 0;
    for (; s < NCHUNK; s += gridDim.x) {
        int snext = s + gridDim.x;
        if (snext < NCHUNK) {
            prefetch_chunk(img, snext, sm_base + (cur ^ 1) * STAGE_B, tid);
        }
        asm volatile("cp.async.commit_group;\n" ::: "memory");
        // all groups except the newest are complete -> chunk s is ready
        asm volatile("cp.async.wait_group 1;\n" ::: "memory");

        int b = s >> 7;
        int hb = s & 127;

        // Per-thread quant scale base: 1/factor for this image.
        float qv = __ldg(&qf[b]);
        float factor = (qv < 50.0f) ? (5000.0f / qv) : (200.0f - 2.0f * qv);
        float rcpF = __fdividef(1.0f, factor);

        const float* sp = smem_dyn + ((size_t)cur * STAGE_B + (size_t)tid * TSTRIDE_B) / 4;

        float x[8][4];
#pragma unroll
        for (int r = 0; r < 8; r++) {
            float4 v = *(const float4*)(sp + r * 4);
            x[r][0] = v.x - 128.0f;
            x[r][1] = v.y - 128.0f;
            x[r][2] = v.z - 128.0f;
            x[r][3] = v.w - 128.0f;
        }

        // Column transform: thread-local, 4 columns.
#pragma unroll
        for (int c = 0; c < 4; c++) {
            dct8(x[0][c], x[1][c], x[2][c], x[3][c],
                 x[4][c], x[5][c], x[6][c], x[7][c]);
        }

        float* ob = out + ((size_t)b << 20) + hb * 128 + wb + (size_t)(q * 4) * 16384;

#pragma unroll
        for (int k = 0; k < 8; k++) {
            float v0 = x[k][0], v1 = x[k][1], v2 = x[k][2], v3 = x[k][3];
            float p0 = __shfl_xor_sync(0xffffffffu, v0, 1);
            float p1 = __shfl_xor_sync(0xffffffffu, v1, 1);
            float p2 = __shfl_xor_sync(0xffffffffu, v2, 1);
            float p3 = __shfl_xor_sync(0xffffffffu, v3, 1);
            // s_i = e_i (q=0) / e_{3-i} (q=1);  d_i = o_i (q=0) / -o_{3-i} (q=1)
            float s0 = v0 + p3, s1 = v1 + p2, s2 = v2 + p1, s3 = v3 + p0;
            float d0 = v0 - p3, d1 = v1 - p2, d2 = v2 - p1, d3 = v3 - p0;
            float ee0 = s0 + s3, ee1 = s1 + s2;
            float u0 = s0 - s3, u1 = s1 - s2;

            float oA = cA0 * ee0 + cA1 * ee1;                      // l = 4q+0
            float oB = cB0 * u0 + cB1 * u1;                        // l = 4q+2
            float oC = cC0 * d0 + cC1 * d1 + cC2 * d2 + cC3 * d3;  // l = 4q+1
            float oD = cD0 * d0 + cD1 * d1 + cD2 * d2 + cD3 * d3;  // l = 4q+3

            float4 qi = *(const float4*)&c_qinv[k * 8 + 4 * q];
            float* ok = ob + (size_t)(k * 8) * 16384;
            ok[0]                 = oA * (qi.x * rcpF);
            ok[(size_t)1 * 16384] = oC * (qi.y * rcpF);
            ok[(size_t)2 * 16384] = oB * (qi.z * rcpF);
            ok[(size_t)3 * 16384] = oD * (qi.w * rcpF);
        }

        cur ^= 1;
    }
}

extern "C" void kernel_launch(void* const* d_in, const int* in_sizes, int n_in,
                              void* d_out, int out_size) {
    const float* img = (const float*)d_in[0];
    const float* qf = (const float*)d_in[1];
    float* out = (float*)d_out;
    static int configured = 0;
    if (!configured) {
        cudaFuncSetAttribute(jpeg_dct_kernel,
                             cudaFuncAttributeMaxDynamicSharedMemorySize,
                             2 * STAGE_B);
        configured = 1;
    }
    // 444 CTAs = 3 CTAs/SM * 148 SMs, grid-striding over 2048 chunks.
    jpeg_dct_kernel<<<444, 256, 2 * STAGE_B>>>(img, qf, out);
}

// round 9
// speedup vs baseline: 1.3815x; 1.3815x over previous
#include <cuda_runtime.h>
#include <cstddef>

// JPEG 8x8 blockify + orthonormal 2D DCT-II + QF quantization.
// image: [16,1,1024,1024] f32, qf: [16] f32 -> out [16,64,128,128] f32.
//
// R8 = R5 (best: 2 threads per 8x8 block, shuffle-pair row DCT, 64 regs,
// 4 CTAs/SM) with ONLY cache-policy changes:
//   - __ldcg input loads  (L2-resident, no L1 alloc; input has zero L1 reuse)
//   - __stcs output stores (evict-first streaming; output is write-once)
// Rationale: input(64MiB)+output(64MiB) vs 126MiB L2. Default-policy writes
// evict the input every replay; streaming writes keep the input L2-resident,
// so reads come from L2 (~234cyc) while DRAM carries the write stream.

#define A0 0.35355339059327373f  // 1/sqrt(8)
#define H1 0.49039264020161522f  // cos(1*pi/16)/2
#define H2 0.46193976625564337f  // cos(2*pi/16)/2
#define H3 0.41573480615127262f  // cos(3*pi/16)/2
#define H4 0.35355339059327376f  // cos(4*pi/16)/2
#define H5 0.27778511650980111f  // cos(5*pi/16)/2
#define H6 0.19134171618254489f  // cos(6*pi/16)/2
#define H7 0.09754516100806413f  // cos(7*pi/16)/2

__constant__ float c_qtab[64] = {
    16.f, 11.f, 10.f, 16.f, 24.f, 40.f, 51.f, 61.f,
    12.f, 12.f, 14.f, 19.f, 26.f, 58.f, 60.f, 55.f,
    14.f, 13.f, 16.f, 24.f, 40.f, 57.f, 69.f, 56.f,
    14.f, 17.f, 22.f, 29.f, 51.f, 87.f, 80.f, 62.f,
    18.f, 22.f, 37.f, 56.f, 68.f, 109.f, 103.f, 77.f,
    24.f, 36.f, 55.f, 64.f, 81.f, 104.f, 113.f, 92.f,
    49.f, 64.f, 78.f, 87.f, 103.f, 121.f, 120.f, 101.f,
    72.f, 92.f, 95.f, 98.f, 112.f, 100.f, 103.f, 99.f};

__device__ __forceinline__ void dct8(float& x0, float& x1, float& x2, float& x3,
                                     float& x4, float& x5, float& x6, float& x7) {
    float e0 = x0 + x7, e1 = x1 + x6, e2 = x2 + x5, e3 = x3 + x4;
    float o0 = x0 - x7, o1 = x1 - x6, o2 = x2 - x5, o3 = x3 - x4;
    float ee0 = e0 + e3, ee1 = e1 + e2;
    float eo0 = e0 - e3, eo1 = e1 - e2;
    x0 = A0 * (ee0 + ee1);
    x4 = H4 * (ee0 - ee1);
    x2 = H2 * eo0 + H6 * eo1;
    x6 = H6 * eo0 - H2 * eo1;
    x1 = H1 * o0 + H3 * o1 + H5 * o2 + H7 * o3;
    x3 = H3 * o0 - H7 * o1 - H1 * o2 - H5 * o3;
    x5 = H5 * o0 - H1 * o1 + H7 * o2 + H3 * o3;
    x7 = H7 * o0 - H5 * o1 + H3 * o2 - H1 * o3;
}

__global__ __launch_bounds__(256, 4) void jpeg_dct_kernel(
    const float* __restrict__ img,
    const float* __restrict__ qf,
    float* __restrict__ out) {
    __shared__ __align__(16) float sScale[64];

    int tid = blockIdx.x * 256 + threadIdx.x;
    int b = tid >> 15;  // 2 threads/block, 32768 threads per image; CTA-uniform

    if (threadIdx.x < 64) {
        float q = qf[b];
        float factor = (q < 50.0f) ? (5000.0f / q) : (200.0f - 2.0f * q);
        sScale[threadIdx.x] = 100.0f / (c_qtab[threadIdx.x] * factor);
    }
    __syncthreads();

    int bid = tid >> 1;      // 8x8 block index
    int h = tid & 1;         // half: columns 4h..4h+3
    int hb = (bid >> 7) & 127;
    int wb = bid & 127;

    // Loads: lane pair covers 32B; warp covers 512B contiguous per row.
    const float* p = img + ((size_t)b << 20) + (size_t)hb * 8192 + wb * 8 + h * 4;

    float x[8][4];
#pragma unroll
    for (int r = 0; r < 8; r++) {
        float4 v = __ldcg((const float4*)(p + (size_t)r * 1024));
        x[r][0] = v.x - 128.0f;
        x[r][1] = v.y - 128.0f;
        x[r][2] = v.z - 128.0f;
        x[r][3] = v.w - 128.0f;
    }

    // Column transform: thread-local, 4 columns.
#pragma unroll
    for (int c = 0; c < 4; c++) {
        dct8(x[0][c], x[1][c], x[2][c], x[3][c],
             x[4][c], x[5][c], x[6][c], x[7][c]);
    }

    // Per-half row-transform coefficients (selected once; both halves then
    // execute the identical arithmetic on s/d):
    //   h=0 emits l = 0,1,2,3 ; h=1 emits l = 4,5,6,7
    bool hi = (h != 0);
    float cA0 = hi ?  H4 :  A0, cA1 = hi ? -H4 :  A0;   // l0 / l4
    float cB0 = hi ? -H6 :  H2, cB1 = hi ?  H2 :  H6;   // l2 / l6
    float cC0 = hi ? -H3 :  H1, cC1 = hi ? -H7 :  H3,   // l1 / l5
          cC2 = hi ?  H1 :  H5, cC3 = hi ? -H5 :  H7;
    float cD0 = hi ?  H1 :  H3, cD1 = hi ? -H3 : -H7,   // l3 / l7
          cD2 = hi ?  H5 : -H1, cD3 = hi ? -H7 : -H5;

    float* ob = out + ((size_t)b << 20) + hb * 128 + wb + (size_t)(h * 4) * 16384;

#pragma unroll
    for (int k = 0; k < 8; k++) {
        float v0 = x[k][0], v1 = x[k][1], v2 = x[k][2], v3 = x[k][3];
        float p0 = __shfl_xor_sync(0xffffffffu, v0, 1);
        float p1 = __shfl_xor_sync(0xffffffffu, v1, 1);
        float p2 = __shfl_xor_sync(0xffffffffu, v2, 1);
        float p3 = __shfl_xor_sync(0xffffffffu, v3, 1);
        // s_i = e_i (h=0) / e_{3-i} (h=1);  d_i = o_i (h=0) / -o_{3-i} (h=1)
        float s0 = v0 + p3, s1 = v1 + p2, s2 = v2 + p1, s3 = v3 + p0;
        float d0 = v0 - p3, d1 = v1 - p2, d2 = v2 - p1, d3 = v3 - p0;
        float ee0 = s0 + s3, ee1 = s1 + s2;
        float u0 = s0 - s3, u1 = s1 - s2;

        float oA = cA0 * ee0 + cA1 * ee1;                              // l = 4h+0
        float oB = cB0 * u0 + cB1 * u1;                                // l = 4h+2
        float oC = cC0 * d0 + cC1 * d1 + cC2 * d2 + cC3 * d3;          // l = 4h+1
        float oD = cD0 * d0 + cD1 * d1 + cD2 * d2 + cD3 * d3;          // l = 4h+3

        float4 sc = *(const float4*)&sScale[k * 8 + 4 * h];
        float* ok = ob + (size_t)(k * 8) * 16384;
        __stcs(ok,                     oA * sc.x);
        __stcs(ok + (size_t)1 * 16384, oC * sc.y);
        __stcs(ok + (size_t)2 * 16384, oB * sc.z);
        __stcs(ok + (size_t)3 * 16384, oD * sc.w);
    }
}

extern "C" void kernel_launch(void* const* d_in, const int* in_sizes, int n_in,
                              void* d_out, int out_size) {
    const float* img = (const float*)d_in[0];
    const float* qf = (const float*)d_in[1];
    float* out = (float*)d_out;
    // 16 images * 16384 blocks * 2 threads = 524288 threads -> 2048 CTAs
    jpeg_dct_kernel<<<2048, 256>>>(img, qf, out);
}